// round 13
// baseline (speedup 1.0000x reference)
#include <cuda_runtime.h>

#define BB 64
#define NN 512
#define EPS 1e-10f

// Scratch (allocation-free rule: __device__ globals; zero-init at load,
// reset by the finalize block each run for graph replay)
__device__ float2   g_items[BB * NN];   // rel-sorted: {disc, exp(score)}
__device__ unsigned g_done[BB];         // per-row prep arrival counters
__device__ float    g_accum = 0.0f;
__device__ unsigned g_count = 0u;

// Single fused kernel. grid (8, 64), 512 threads.
// Phase 1: block q ranks items [q*64, q*64+64) with 8 thr/item (64 j's each);
//          every block redundantly computes row constants (balanced).
// Row barrier: fence + arrive + poll on g_done[row].
// Phase 2: bucket-segmented valid pairs (5 instr/pair). Thread handles items
//          (tt, 511-tt), tt = t&255; j-chunk c = q*2 + (t>>8) (16 chunks).
__global__ __launch_bounds__(512, 3)
void lr_fused(const float* __restrict__ scores,
              const float* __restrict__ relevance,
              float* __restrict__ out) {
    const int q   = blockIdx.x;      // 0..7
    const int row = blockIdx.y;
    const int t   = threadIdx.x;

    __shared__ float2 buf[NN];       // phase1: {score, rel}; phase2: {d, E}
    __shared__ int    counts[5];
    __shared__ int    stS[6];        // segment starts {0, b4, b3, b2, b1, 512}
    __shared__ float  wred[16];

    // ---------------- Phase 1: prep ----------------
    if (t < 5) counts[t] = 0;
    float s0 = scores[row * NN + t];
    float r0 = relevance[row * NN + t];
    buf[t] = make_float2(s0, r0);
    __syncthreads();

    // histogram via ballots (4 atomics per warp, lane 0)
    {
        int a = (int)r0;
        int h1 = __popc(__ballot_sync(~0u, a == 1));
        int h2 = __popc(__ballot_sync(~0u, a == 2));
        int h3 = __popc(__ballot_sync(~0u, a == 3));
        int h4 = __popc(__ballot_sync(~0u, a == 4));
        if ((t & 31) == 0) {
            atomicAdd(&counts[1], h1); atomicAdd(&counts[2], h2);
            atomicAdd(&counts[3], h3); atomicAdd(&counts[4], h4);
        }
    }

    // rank scan: 8 thr/item, j = 8*jj+part; tie-break (j<i) via loop split
    const int   i    = q * 64 + (t >> 3);
    const int   part = t & 7;
    const float2 self = buf[i];
    const float si  = self.x;
    const float rif = self.y;
    const int   thr = (i - part + 7) >> 3;    // #jj with 8jj+part < i

    int rk = 0, same = 0, jj = 0;
    #pragma unroll 8
    for (; jj < thr; ++jj) {                  // region j < i
        float2 v = buf[8 * jj + part];
        rk   += (v.x >= si);                  // (x>si) || (x==si && j<i)
        same += (v.y == rif);
    }
    #pragma unroll 8
    for (; jj < 64; ++jj)                     // region j >= i (incl. self)
        rk += (buf[8 * jj + part].x > si);

    int pk = rk | (same << 16);
    pk += __shfl_down_sync(0xffffffffu, pk, 4, 8);
    pk += __shfl_down_sync(0xffffffffu, pk, 2, 8);
    pk += __shfl_down_sync(0xffffffffu, pk, 1, 8);

    __syncthreads();                          // histogram complete
    const int c4 = counts[4], c3 = counts[3], c2 = counts[2], c1 = counts[1];
    const int b4 = c4, b3 = b4 + c3, b2 = b3 + c2, b1 = b2 + c1;

    if (part == 0) {
        int rkT   = pk & 0xffff;
        int sameT = pk >> 16;
        int r = (int)rif;
        int base = (r == 4) ? 0 : (r == 3) ? b4 : (r == 2) ? b3
                 : (r == 1) ? b2 : b1;
        float d = __fdividef(1.0f, __log2f((float)(rkT + 3)));  // rank = rkT+1
        g_items[row * NN + base + sameT] = make_float2(d, __expf(si));
    }

    // row scale: redundant in EVERY block (one position per thread)
    float scale = 0.0f;                       // valid on t==0
    {
        float gl = t < b4 ? 15.f : t < b3 ? 7.f : t < b2 ? 3.f : t < b1 ? 1.f : 0.f;
        float v = __fdividef(gl, __log2f((float)(t + 2)));
        #pragma unroll
        for (int o = 16; o > 0; o >>= 1) v += __shfl_down_sync(0xffffffffu, v, o);
        if ((t & 31) == 0) wred[t >> 5] = v;
        if (t == 0) {
            stS[0] = 0; stS[1] = b4; stS[2] = b3;
            stS[3] = b2; stS[4] = b1; stS[5] = NN;
        }
        __syncthreads();                      // also orders g_items stores
        if (t == 0) {
            float idcg = 0.0f;
            #pragma unroll
            for (int k = 0; k < 16; ++k) idcg += wred[k];
            idcg = fmaxf(idcg, EPS);
            int c0 = NN - b1;
            float sq = (float)c4 * c4 + (float)c3 * c3 + (float)c2 * c2 +
                       (float)c1 * c1 + (float)c0 * c0;
            float cntf = 0.5f * ((float)NN * NN - sq);
            scale = 0.6931471805599453f / (idcg * (cntf + EPS)) / (float)BB;
        }
    }

    // ---------------- Row barrier ----------------
    if (t == 0) {
        __threadfence();
        atomicAdd(&g_done[row], 1u);
        while (atomicAdd(&g_done[row], 0u) < 8u) {}
    }
    __syncthreads();

    // ---------------- Phase 2: bucket-segmented valid pairs ----------------
    buf[t] = __ldcg(&g_items[row * NN + t]);  // {d, E} at sorted positions
    __syncthreads();

    const int c  = q * 2 + (t >> 8);          // j-chunk 0..15
    const int tt = t & 255;

    float acc = 0.0f;
    #pragma unroll
    for (int it = 0; it < 2; ++it) {
        const int p = it ? (NN - 1 - tt) : tt;
        int bk = (p >= stS[1]) + (p >= stS[2]) + (p >= stS[3]) + (p >= stS[4]);
        float gi = (float)((16 >> bk) - 1);
        int bkw = __shfl_sync(0xffffffffu, bk, it ? 31 : 0);   // warp-min bucket
        float2 me = buf[p];
        float di   = me.x;
        float Einv = __fdividef(1.0f, me.y);                   // exp(-s_i)
        int lo  = stS[bkw + 1];                                // bkw==4 -> 512
        int len = NN - lo;
        int j0 = lo + ((c * len) >> 4);
        int j1 = lo + (((c + 1) * len) >> 4);

        for (int s = bkw + 1; s < 5; ++s) {                    // warp-uniform
            int a = max(j0, stS[s]);
            int b = min(j1, stS[s + 1]);
            float C = fmaxf(gi - (float)((16 >> s) - 1), 0.0f);
            float partsum = 0.0f;
            #pragma unroll 4
            for (int j = a; j < b; ++j) {                      // broadcast LDS
                float2 v = buf[j];
                float dd = di - v.x;
                float lg = __log2f(fmaf(Einv, v.y, 1.0f));
                partsum = fmaf(fabsf(dd), lg, partsum);
            }
            acc = fmaf(C, partsum, acc);
        }
    }

    // block reduce (16 warps)
    #pragma unroll
    for (int o = 16; o > 0; o >>= 1) acc += __shfl_down_sync(0xffffffffu, acc, o);
    if ((t & 31) == 0) wred[t >> 5] = acc;
    __syncthreads();
    if (t == 0) {
        float bs = 0.0f;
        #pragma unroll
        for (int k = 0; k < 16; ++k) bs += wred[k];
        atomicAdd(&g_accum, bs * scale);
        __threadfence();
        unsigned n = atomicAdd(&g_count, 1u);
        if (n == 8u * BB - 1u) {             // last block finalizes + resets
            out[0] = atomicAdd(&g_accum, 0.0f);
            g_accum = 0.0f;
            g_count = 0u;
            #pragma unroll
            for (int k = 0; k < BB; ++k) g_done[k] = 0u;
        }
    }
}

extern "C" void kernel_launch(void* const* d_in, const int* in_sizes, int n_in,
                              void* d_out, int out_size) {
    const float* scores    = (const float*)d_in[0];
    const float* relevance = (const float*)d_in[1];
    float* out = (float*)d_out;

    lr_fused<<<dim3(8, BB), 512>>>(scores, relevance, out);
}

// round 14
// speedup vs baseline: 1.0666x; 1.0666x over previous
#include <cuda_runtime.h>

#define BB 64
#define NN 512
#define EPS 1e-10f

// Scratch (allocation-free rule: __device__ globals; zero-init at load,
// reset by the finalize block each run for graph replay)
__device__ float2   g_items[BB * NN];   // rel-sorted: {disc, exp(score)}
__device__ unsigned g_slot[BB * 5];     // within-bucket placement counters
__device__ unsigned g_done[BB];         // per-row prep arrival counters
__device__ float    g_accum = 0.0f;
__device__ unsigned g_count = 0u;

// Single fused kernel. grid (8, 64), 256 threads (R12 skeleton).
// Phase 1: block q ranks items [q*64, q*64+64) with a VECTORIZED score-only
//          scan (float4: 2.25 issue slots per j). Placement via global atomic
//          bucket slots. Every block redundantly computes row constants.
// Row barrier: fence + arrive + poll on g_done[row].
// Phase 2: bucket-segmented valid pairs (5 instr/pair), warp-uniform bounds.
__global__ __launch_bounds__(256, 8)
void lr_fused(const float* __restrict__ scores,
              const float* __restrict__ relevance,
              float* __restrict__ out) {
    const int q   = blockIdx.x;      // 0..7
    const int row = blockIdx.y;
    const int t   = threadIdx.x;

    __shared__ float2 buf[NN];       // phase1 alias: float ss[512]; ph2: {d,E}
    __shared__ int    counts[5];
    __shared__ int    stS[6];        // segment starts {0, b4, b3, b2, b1, 512}
    __shared__ float  wred[8];

    float* ss = reinterpret_cast<float*>(buf);

    // ---------------- Phase 1: prep ----------------
    if (t < 5) counts[t] = 0;
    ss[t]       = scores[row * NN + t];
    ss[t + 256] = scores[row * NN + t + 256];
    int r0 = (int)relevance[row * NN + t];
    int r1 = (int)relevance[row * NN + t + 256];
    __syncthreads();

    // histogram via ballots (4 atomics per warp, lane 0)
    {
        int h1 = __popc(__ballot_sync(~0u, r0 == 1)) + __popc(__ballot_sync(~0u, r1 == 1));
        int h2 = __popc(__ballot_sync(~0u, r0 == 2)) + __popc(__ballot_sync(~0u, r1 == 2));
        int h3 = __popc(__ballot_sync(~0u, r0 == 3)) + __popc(__ballot_sync(~0u, r1 == 3));
        int h4 = __popc(__ballot_sync(~0u, r0 == 4)) + __popc(__ballot_sync(~0u, r1 == 4));
        if ((t & 31) == 0) {
            atomicAdd(&counts[1], h1); atomicAdd(&counts[2], h2);
            atomicAdd(&counts[3], h3); atomicAdd(&counts[4], h4);
        }
    }

    // vectorized rank scan: 4 thr/item; thread `part` covers vectors m=4mm+part.
    // Vector fully below i (4m+3 < i): compare >=; fully above (4m > i): >;
    // boundary vector m == i>>2 handled element-wise (self contributes 0).
    const int   i    = q * 64 + (t >> 2);
    const int   part = t & 3;
    const float si   = ss[i];
    const int   Mlt  = i >> 2;                     // index of boundary vector
    const int   thrA = (Mlt - part + 3) >> 2;      // #mm with 4mm+part < Mlt
    const int   thrB = (Mlt - part + 4) >> 2;      // first mm with 4mm+part > Mlt
    const float4* ss4 = reinterpret_cast<const float4*>(ss);

    int rk = 0;
    #pragma unroll 4
    for (int mm = 0; mm < thrA; ++mm) {            // vectors fully below
        float4 v = ss4[4 * mm + part];
        rk += (v.x >= si) + (v.y >= si) + (v.z >= si) + (v.w >= si);
    }
    if (thrA != thrB) {                            // boundary vector owned
        float4 v = ss4[Mlt];
        int e0 = i & 3;                            // self element
        rk += (0 < e0) ? (v.x >= si) : (v.x > si);
        rk += (1 < e0) ? (v.y >= si) : (v.y > si);
        rk += (2 < e0) ? (v.z >= si) : (v.z > si);
        rk += (3 < e0) ? (v.w >= si) : (v.w > si);
    }
    #pragma unroll 4
    for (int mm = thrB; mm < 32; ++mm) {           // vectors fully above
        float4 v = ss4[4 * mm + part];
        rk += (v.x > si) + (v.y > si) + (v.z > si) + (v.w > si);
    }
    rk += __shfl_down_sync(0xffffffffu, rk, 2, 4);
    rk += __shfl_down_sync(0xffffffffu, rk, 1, 4);

    __syncthreads();                               // histogram complete
    const int c4 = counts[4], c3 = counts[3], c2 = counts[2], c1 = counts[1];
    const int b4 = c4, b3 = b4 + c3, b2 = b3 + c2, b1 = b2 + c1;

    if (part == 0) {
        int ri = (int)relevance[row * NN + i];     // own item's relevance
        int base = (ri == 4) ? 0 : (ri == 3) ? b4 : (ri == 2) ? b3
                 : (ri == 1) ? b2 : b1;
        unsigned slot = atomicAdd(&g_slot[row * 5 + ri], 1u);
        float d = __fdividef(1.0f, __log2f((float)(rk + 3)));  // rank = rk+1
        g_items[row * NN + base + (int)slot] = make_float2(d, __expf(si));
    }

    // row scale: redundant in EVERY block (balanced)
    float scale = 0.0f;                            // valid on t==0
    {
        float v = 0.0f;
        #pragma unroll
        for (int h = 0; h < 2; ++h) {
            int p = t + h * 256;
            float gl = p < b4 ? 15.f : p < b3 ? 7.f : p < b2 ? 3.f : p < b1 ? 1.f : 0.f;
            v += __fdividef(gl, __log2f((float)(p + 2)));
        }
        #pragma unroll
        for (int o = 16; o > 0; o >>= 1) v += __shfl_down_sync(0xffffffffu, v, o);
        if ((t & 31) == 0) wred[t >> 5] = v;
        if (t == 0) {
            stS[0] = 0; stS[1] = b4; stS[2] = b3;
            stS[3] = b2; stS[4] = b1; stS[5] = NN;
        }
        __syncthreads();                           // also orders g_items stores
        if (t == 0) {
            float idcg = fmaxf(wred[0] + wred[1] + wred[2] + wred[3] +
                               wred[4] + wred[5] + wred[6] + wred[7], EPS);
            int c0 = NN - b1;
            float sq = (float)c4 * c4 + (float)c3 * c3 + (float)c2 * c2 +
                       (float)c1 * c1 + (float)c0 * c0;
            float cntf = 0.5f * ((float)NN * NN - sq);
            scale = 0.6931471805599453f / (idcg * (cntf + EPS)) / (float)BB;
        }
    }

    // ---------------- Row barrier ----------------
    if (t == 0) {
        __threadfence();
        atomicAdd(&g_done[row], 1u);
        while (atomicAdd(&g_done[row], 0u) < 8u) {}
    }
    __syncthreads();

    // ---------------- Phase 2: bucket-segmented valid pairs ----------------
    reinterpret_cast<float4*>(buf)[t] =
        __ldcg(reinterpret_cast<const float4*>(g_items + row * NN) + t);
    __syncthreads();

    float acc = 0.0f;
    #pragma unroll
    for (int it = 0; it < 2; ++it) {
        const int p = it ? (NN - 1 - t) : t;
        int bk = (p >= stS[1]) + (p >= stS[2]) + (p >= stS[3]) + (p >= stS[4]);
        float gi = (float)((16 >> bk) - 1);
        int bkw = __shfl_sync(0xffffffffu, bk, it ? 31 : 0);   // warp-min bucket
        float2 me = buf[p];
        float di   = me.x;
        float Einv = __fdividef(1.0f, me.y);                   // exp(-s_i)
        int lo  = stS[bkw + 1];                                // bkw==4 -> 512
        int len = NN - lo;
        int j0 = lo + ((q * len) >> 3);
        int j1 = lo + (((q + 1) * len) >> 3);

        for (int s = bkw + 1; s < 5; ++s) {                    // warp-uniform
            int a = max(j0, stS[s]);
            int b = min(j1, stS[s + 1]);
            float C = fmaxf(gi - (float)((16 >> s) - 1), 0.0f);
            float partsum = 0.0f;
            #pragma unroll 4
            for (int j = a; j < b; ++j) {                      // broadcast LDS
                float2 v = buf[j];
                float dd = di - v.x;
                float lg = __log2f(fmaf(Einv, v.y, 1.0f));
                partsum = fmaf(fabsf(dd), lg, partsum);
            }
            acc = fmaf(C, partsum, acc);
        }
    }

    // block reduce (8 warps)
    #pragma unroll
    for (int o = 16; o > 0; o >>= 1) acc += __shfl_down_sync(0xffffffffu, acc, o);
    if ((t & 31) == 0) wred[t >> 5] = acc;
    __syncthreads();
    if (t == 0) {
        float bs = wred[0] + wred[1] + wred[2] + wred[3] +
                   wred[4] + wred[5] + wred[6] + wred[7];
        atomicAdd(&g_accum, bs * scale);
        __threadfence();
        unsigned n = atomicAdd(&g_count, 1u);
        if (n == 8u * BB - 1u) {             // last block finalizes + resets
            out[0] = atomicAdd(&g_accum, 0.0f);
            g_accum = 0.0f;
            g_count = 0u;
            #pragma unroll 4
            for (int k = 0; k < BB; ++k)     g_done[k] = 0u;
            #pragma unroll 4
            for (int k = 0; k < BB * 5; ++k) g_slot[k] = 0u;
        }
    }
}

extern "C" void kernel_launch(void* const* d_in, const int* in_sizes, int n_in,
                              void* d_out, int out_size) {
    const float* scores    = (const float*)d_in[0];
    const float* relevance = (const float*)d_in[1];
    float* out = (float*)d_out;

    lr_fused<<<dim3(8, BB), 256>>>(scores, relevance, out);
}

// round 15
// speedup vs baseline: 1.1783x; 1.1048x over previous
#include <cuda_runtime.h>

#define BB 64
#define NN 512
#define EPS 1e-10f

// Scratch (allocation-free rule: __device__ globals; zero-init at load,
// reset by the finalize block each run for graph replay)
__device__ float2   g_items[BB * NN];   // rel-sorted: {disc, exp(score)}
__device__ unsigned g_done[BB];         // per-row prep arrival counters
__device__ float    g_accum = 0.0f;
__device__ unsigned g_count = 0u;

// Single fused kernel. grid (8, 64), 256 threads (R12 skeleton).
// Phase 1: block q ranks items [q*64, q*64+64). Rank via vectorized float4
//          score scan (~2.25 slots/j); within-bucket index via SIMD byte scan
//          over packed relevance (~0.75 slots/j) -> deterministic placement,
//          no atomics / no LDG on the barrier critical path.
// Row barrier: fence + arrive + poll on g_done[row].
// Phase 2: bucket-segmented valid pairs (5 instr/pair), warp-uniform bounds.
__global__ __launch_bounds__(256, 8)
void lr_fused(const float* __restrict__ scores,
              const float* __restrict__ relevance,
              float* __restrict__ out) {
    const int q   = blockIdx.x;      // 0..7
    const int row = blockIdx.y;
    const int t   = threadIdx.x;

    __shared__ float2   buf[NN];     // ph1 alias: float ss[512]; ph2: {d,E}
    __shared__ unsigned srelW[NN / 4]; // relevance packed as bytes
    __shared__ int      counts[5];
    __shared__ int      stS[6];      // segment starts {0, b4, b3, b2, b1, 512}
    __shared__ float    wred[8];

    float* ss = reinterpret_cast<float*>(buf);
    unsigned char* srel = reinterpret_cast<unsigned char*>(srelW);

    // ---------------- Phase 1: prep ----------------
    if (t < 5) counts[t] = 0;
    ss[t]       = scores[row * NN + t];
    ss[t + 256] = scores[row * NN + t + 256];
    int r0 = (int)relevance[row * NN + t];
    int r1 = (int)relevance[row * NN + t + 256];
    srel[t]       = (unsigned char)r0;
    srel[t + 256] = (unsigned char)r1;
    __syncthreads();

    // histogram via ballots (4 atomics per warp, lane 0)
    {
        int h1 = __popc(__ballot_sync(~0u, r0 == 1)) + __popc(__ballot_sync(~0u, r1 == 1));
        int h2 = __popc(__ballot_sync(~0u, r0 == 2)) + __popc(__ballot_sync(~0u, r1 == 2));
        int h3 = __popc(__ballot_sync(~0u, r0 == 3)) + __popc(__ballot_sync(~0u, r1 == 3));
        int h4 = __popc(__ballot_sync(~0u, r0 == 4)) + __popc(__ballot_sync(~0u, r1 == 4));
        if ((t & 31) == 0) {
            atomicAdd(&counts[1], h1); atomicAdd(&counts[2], h2);
            atomicAdd(&counts[3], h3); atomicAdd(&counts[4], h4);
        }
    }

    // ---- vectorized rank scan: 4 thr/item, vectors m = 4*mm+part ----
    // Vector fully below i: >=; fully above: >; boundary vector element-wise.
    const int   i    = q * 64 + (t >> 2);
    const int   part = t & 3;
    const float si   = ss[i];
    const int   Mb   = i >> 2;                     // boundary vector index
    const int   thrA = (Mb - part + 3) >> 2;       // #mm with 4mm+part < Mb
    const bool  ownB = ((Mb & 3) == part);
    const float4* ss4 = reinterpret_cast<const float4*>(ss);

    int rk = 0;
    #pragma unroll 4
    for (int mm = 0; mm < thrA; ++mm) {            // vectors fully below
        float4 v = ss4[4 * mm + part];
        rk += (v.x >= si) + (v.y >= si) + (v.z >= si) + (v.w >= si);
    }
    if (ownB) {                                    // boundary vector
        float4 v = ss4[Mb];
        int e0 = i & 3;                            // self element
        rk += (0 < e0) ? (v.x >= si) : (v.x > si);
        rk += (1 < e0) ? (v.y >= si) : (v.y > si);
        rk += (2 < e0) ? (v.z >= si) : (v.z > si);
        rk += (3 < e0) ? (v.w >= si) : (v.w > si);
    }
    {
        const int thrB = (Mb - part + 4) >> 2;     // first mm with 4mm+part > Mb
        #pragma unroll 4
        for (int mm = thrB; mm < 32; ++mm) {       // vectors fully above
            float4 v = ss4[4 * mm + part];
            rk += (v.x > si) + (v.y > si) + (v.z > si) + (v.w > si);
        }
    }

    // ---- SIMD byte scan for same-rel count (j < i, rel_j == rel_i) ----
    const int ri = (int)((srelW[Mb] >> (8 * (i & 3))) & 0xFFu);
    {
        const unsigned rrep = (unsigned)ri * 0x01010101u;
        const int W     = i >> 2;                  // boundary word (= Mb)
        const int nFull = (W - part + 3) >> 2;     // #mm with 4mm+part < W
        int same = 0;
        #pragma unroll 4
        for (int mm = 0; mm < nFull; ++mm) {
            unsigned x = srelW[4 * mm + part];
            same += __popc(__vcmpeq4(x, rrep) & 0x01010101u);
        }
        if (ownB) {                                // partial boundary word
            unsigned m = (i & 3) ? (0xFFFFFFFFu >> (32 - 8 * (i & 3))) : 0u;
            same += __popc(__vcmpeq4(srelW[W], rrep) & 0x01010101u & m);
        }
        rk |= same << 16;                          // pack; no cross-field carry
    }
    rk += __shfl_down_sync(0xffffffffu, rk, 2, 4);
    rk += __shfl_down_sync(0xffffffffu, rk, 1, 4);

    __syncthreads();                               // histogram complete
    const int c4 = counts[4], c3 = counts[3], c2 = counts[2], c1 = counts[1];
    const int b4 = c4, b3 = b4 + c3, b2 = b3 + c2, b1 = b2 + c1;

    if (part == 0) {
        int rkT   = rk & 0xffff;
        int sameT = rk >> 16;
        int base = (ri == 4) ? 0 : (ri == 3) ? b4 : (ri == 2) ? b3
                 : (ri == 1) ? b2 : b1;
        float d = __fdividef(1.0f, __log2f((float)(rkT + 3)));  // rank = rkT+1
        g_items[row * NN + base + sameT] = make_float2(d, __expf(si));
    }

    // row scale: redundant in EVERY block (balanced)
    float scale = 0.0f;                            // valid on t==0
    {
        float v = 0.0f;
        #pragma unroll
        for (int h = 0; h < 2; ++h) {
            int p = t + h * 256;
            float gl = p < b4 ? 15.f : p < b3 ? 7.f : p < b2 ? 3.f : p < b1 ? 1.f : 0.f;
            v += __fdividef(gl, __log2f((float)(p + 2)));
        }
        #pragma unroll
        for (int o = 16; o > 0; o >>= 1) v += __shfl_down_sync(0xffffffffu, v, o);
        if ((t & 31) == 0) wred[t >> 5] = v;
        if (t == 0) {
            stS[0] = 0; stS[1] = b4; stS[2] = b3;
            stS[3] = b2; stS[4] = b1; stS[5] = NN;
        }
        __syncthreads();                           // also orders g_items stores
        if (t == 0) {
            float idcg = fmaxf(wred[0] + wred[1] + wred[2] + wred[3] +
                               wred[4] + wred[5] + wred[6] + wred[7], EPS);
            int c0 = NN - b1;
            float sq = (float)c4 * c4 + (float)c3 * c3 + (float)c2 * c2 +
                       (float)c1 * c1 + (float)c0 * c0;
            float cntf = 0.5f * ((float)NN * NN - sq);
            scale = 0.6931471805599453f / (idcg * (cntf + EPS)) / (float)BB;
        }
    }

    // ---------------- Row barrier ----------------
    if (t == 0) {
        __threadfence();
        atomicAdd(&g_done[row], 1u);
        while (atomicAdd(&g_done[row], 0u) < 8u) {}
    }
    __syncthreads();

    // ---------------- Phase 2: bucket-segmented valid pairs ----------------
    reinterpret_cast<float4*>(buf)[t] =
        __ldcg(reinterpret_cast<const float4*>(g_items + row * NN) + t);
    __syncthreads();

    float acc = 0.0f;
    #pragma unroll
    for (int it = 0; it < 2; ++it) {
        const int p = it ? (NN - 1 - t) : t;
        int bk = (p >= stS[1]) + (p >= stS[2]) + (p >= stS[3]) + (p >= stS[4]);
        float gi = (float)((16 >> bk) - 1);
        int bkw = __shfl_sync(0xffffffffu, bk, it ? 31 : 0);   // warp-min bucket
        float2 me = buf[p];
        float di   = me.x;
        float Einv = __fdividef(1.0f, me.y);                   // exp(-s_i)
        int lo  = stS[bkw + 1];                                // bkw==4 -> 512
        int len = NN - lo;
        int j0 = lo + ((q * len) >> 3);
        int j1 = lo + (((q + 1) * len) >> 3);

        for (int s = bkw + 1; s < 5; ++s) {                    // warp-uniform
            int a = max(j0, stS[s]);
            int b = min(j1, stS[s + 1]);
            float C = fmaxf(gi - (float)((16 >> s) - 1), 0.0f);
            float partsum = 0.0f;
            #pragma unroll 4
            for (int j = a; j < b; ++j) {                      // broadcast LDS
                float2 v = buf[j];
                float dd = di - v.x;
                float lg = __log2f(fmaf(Einv, v.y, 1.0f));
                partsum = fmaf(fabsf(dd), lg, partsum);
            }
            acc = fmaf(C, partsum, acc);
        }
    }

    // block reduce (8 warps)
    #pragma unroll
    for (int o = 16; o > 0; o >>= 1) acc += __shfl_down_sync(0xffffffffu, acc, o);
    if ((t & 31) == 0) wred[t >> 5] = acc;
    __syncthreads();
    if (t == 0) {
        float bs = wred[0] + wred[1] + wred[2] + wred[3] +
                   wred[4] + wred[5] + wred[6] + wred[7];
        atomicAdd(&g_accum, bs * scale);
        __threadfence();
        unsigned n = atomicAdd(&g_count, 1u);
        if (n == 8u * BB - 1u) {             // last block finalizes + resets
            out[0] = atomicAdd(&g_accum, 0.0f);
            g_accum = 0.0f;
            g_count = 0u;
            #pragma unroll 4
            for (int k = 0; k < BB; ++k) g_done[k] = 0u;
        }
    }
}

extern "C" void kernel_launch(void* const* d_in, const int* in_sizes, int n_in,
                              void* d_out, int out_size) {
    const float* scores    = (const float*)d_in[0];
    const float* relevance = (const float*)d_in[1];
    float* out = (float*)d_out;

    lr_fused<<<dim3(8, BB), 256>>>(scores, relevance, out);
}